// round 8
// baseline (speedup 1.0000x reference)
#include <cuda_runtime.h>

// CRF forward scan, probability domain (scaled HMM forward).
// Champion frame: 1 CTA/batch, 128 threads, full E-row per thread as 64
// packed f32x2 regs, 8 accumulator chains, one __syncthreads per step.
// R8: renorm bookkeeping (REDUX.MAX + wmax store) moved OFF the pre-barrier
// critical path to the top of the next iteration, operating on the register
// copy of s. rz becomes a lag-2 power-of-two normalizer (exactly accounted
// in eacc; only affects dynamic range, bounded << 2^127).

#define KDIM 128
typedef unsigned long long u64;

__device__ __forceinline__ void fma2(u64& a, u64 x, u64 p) {
    asm("fma.rn.f32x2 %0, %1, %2, %0;" : "+l"(a) : "l"(x), "l"(p));
}
__device__ __forceinline__ u64 add2(u64 a, u64 b) {
    u64 r; asm("add.rn.f32x2 %0, %1, %2;" : "=l"(r) : "l"(a), "l"(b)); return r;
}
__device__ __forceinline__ u64 pack2(float lo, float hi) {
    u64 r; asm("mov.b64 %0, {%1, %2};" : "=l"(r) : "f"(lo), "f"(hi)); return r;
}

__global__ __launch_bounds__(128, 1)
void crf_fwd_kernel(const float* __restrict__ y,
                    const float* __restrict__ mask,
                    const float* __restrict__ trans,
                    float* __restrict__ out,
                    int T) {
    const int b    = blockIdx.x;
    const int i    = threadIdx.x;      // 0..127 : output state
    const int lane = i & 31;
    const int warp = i >> 5;

    __shared__ __align__(16) float    pbuf[2][KDIM];
    __shared__ __align__(16) unsigned wmax[2][4];   // parity slots
    __shared__ float redf[4];
    __shared__ int   len_sh;

    // ---- one-time: E row = exp(trans[i][:]) as 64 packed f32x2 regs ----
    u64 E2[64];
    {
        const float4* t4 = reinterpret_cast<const float4*>(trans + (size_t)i * KDIM);
        #pragma unroll
        for (int q = 0; q < 32; q++) {
            float4 v = t4[q];
            E2[2*q]   = pack2(expf(v.x), expf(v.y));
            E2[2*q+1] = pack2(expf(v.z), expf(v.w));
        }
    }

    // ---- init state, renorm buffers, length ----
    if (i == 0) len_sh = 0;
    float s = (i == 2) ? 1.0f : 0.0f;             // SOS_IDX = 2
    pbuf[0][i] = s;
    if (i < 8) wmax[i >> 2][i & 3] = 0x3f800000u; // both parity slots = 1.0
    __syncthreads();
    {
        const float* mb = mask + (size_t)b * T;
        int cnt = 0;
        for (int t = i; t < T; t += KDIM) cnt += (mb[t] != 0.0f);
        cnt = __reduce_add_sync(0xffffffffu, cnt);
        if (lane == 0) atomicAdd(&len_sh, cnt);
    }
    __syncthreads();
    const int len = len_sh;

    // ---- y prefetch pipeline (3 deep), pointer-increment ----
    const float* yb   = y + (size_t)b * T * KDIM + i;
    const float* yp   = yb + 3 * KDIM;
    const float* yend = yb + (size_t)T * KDIM;
    float ey = 0.0f, y1 = 0.0f, y2 = 0.0f;
    if (len > 0) ey = __expf(yb[0]);
    if (1 < T)   y1 = yb[KDIM];
    if (2 < T)   y2 = yb[2 * KDIM];

    int cur  = 0;
    int eacc = 0;

    for (int t = 0; t < len; t++) {
        // rz from lag-2 max (slot written at top of t-1, one barrier ago).
        // Issue the LDS first so its 29-cyc latency overlaps what follows.
        uint4 wm4 = *reinterpret_cast<const uint4*>(wmax[(t + 1) & 1]);

        // bookkeeping for s_{t-1} (register copy) — off the critical path,
        // overlaps the FFMA issue stream below. Read next iteration.
        unsigned wmv = __reduce_max_sync(0xffffffffu, __float_as_uint(s));
        if (lane == 0) wmax[t & 1][warp] = wmv;

        unsigned mbits = max(max(wm4.x, wm4.y), max(wm4.z, wm4.w));
        int Ee     = (int)(mbits >> 23);
        float rz   = __uint_as_float((unsigned)(254 - Ee) << 23); // 2^(127-Ee)
        float eyrz = ey * rz;
        eacc      += Ee - 127;

        // matvec: q_i = sum_j E[i][j] * s_t[j]  (32x LDS.128 + 64x fma.f32x2)
        const ulonglong2* p2 = reinterpret_cast<const ulonglong2*>(pbuf[cur]);
        u64 a0=0,a1=0,a2=0,a3=0,a4=0,a5=0,a6=0,a7=0;
        #pragma unroll
        for (int q = 0; q < 8; q++) {
            ulonglong2 v0 = p2[4*q+0];
            ulonglong2 v1 = p2[4*q+1];
            ulonglong2 v2 = p2[4*q+2];
            ulonglong2 v3 = p2[4*q+3];
            fma2(a0, E2[8*q+0], v0.x);
            fma2(a1, E2[8*q+1], v0.y);
            fma2(a2, E2[8*q+2], v1.x);
            fma2(a3, E2[8*q+3], v1.y);
            fma2(a4, E2[8*q+4], v2.x);
            fma2(a5, E2[8*q+5], v2.y);
            fma2(a6, E2[8*q+6], v3.x);
            fma2(a7, E2[8*q+7], v3.y);
        }
        u64 aa = add2(add2(add2(a0,a1), add2(a2,a3)),
                      add2(add2(a4,a5), add2(a6,a7)));
        float qlo, qhi;
        asm("mov.b64 {%0, %1}, %2;" : "=f"(qlo), "=f"(qhi) : "l"(aa));
        s = (qlo + qhi) * eyrz;                     // s >= 0 always
        pbuf[cur ^ 1][i] = s;                       // straight to barrier

        // rotate y pipeline (independent; fills issue while STS drains)
        ey = __expf(y1);
        y1 = y2;
        y2 = (yp < yend) ? *yp : 0.0f;
        yp += KDIM;

        __syncthreads();
        cur ^= 1;
    }

    // ---- final: out[b] = log(sum_i s_i) + eacc*ln2 ----
    float e = s;
    e += __shfl_xor_sync(0xffffffffu, e, 16);
    e += __shfl_xor_sync(0xffffffffu, e, 8);
    e += __shfl_xor_sync(0xffffffffu, e, 4);
    e += __shfl_xor_sync(0xffffffffu, e, 2);
    e += __shfl_xor_sync(0xffffffffu, e, 1);
    if (lane == 0) redf[warp] = e;
    __syncthreads();
    if (i == 0) {
        float tot = (redf[0] + redf[1]) + (redf[2] + redf[3]);
        out[b] = logf(tot) + (float)((double)eacc * 0.6931471805599453);
    }
}

extern "C" void kernel_launch(void* const* d_in, const int* in_sizes, int n_in,
                              void* d_out, int out_size) {
    const float* y     = (const float*)d_in[0];   // (B, T, K) f32
    const float* mask  = (const float*)d_in[1];   // (B, T)    f32
    const float* trans = (const float*)d_in[2];   // (K, K)    f32
    float* out = (float*)d_out;                   // (B,)      f32

    const int B = out_size;                       // 64
    const int T = in_sizes[1] / B;                // 256

    crf_fwd_kernel<<<B, 128>>>(y, mask, trans, out, T);
}

// round 9
// speedup vs baseline: 1.1782x; 1.1782x over previous
#include <cuda_runtime.h>

// CRF forward scan, probability domain (scaled HMM forward).
// Champion frame: 1 CTA/batch, 128 threads, full E-row per thread as 64
// packed f32x2 regs, 8 accumulator chains, one __syncthreads per step.
// R9: NO cross-thread reduction for renormalization. The per-step
// power-of-two scale is taken from the exponent of s[3] (state 3 is
// strictly positive from step 1; spread vs max is bounded ~2^43, well
// inside fp32 range). eacc accounts exactly for the applied scale.

#define KDIM 128
typedef unsigned long long u64;

__device__ __forceinline__ void fma2(u64& a, u64 x, u64 p) {
    asm("fma.rn.f32x2 %0, %1, %2, %0;" : "+l"(a) : "l"(x), "l"(p));
}
__device__ __forceinline__ u64 add2(u64 a, u64 b) {
    u64 r; asm("add.rn.f32x2 %0, %1, %2;" : "=l"(r) : "l"(a), "l"(b)); return r;
}
__device__ __forceinline__ u64 pack2(float lo, float hi) {
    u64 r; asm("mov.b64 %0, {%1, %2};" : "=l"(r) : "f"(lo), "f"(hi)); return r;
}

__global__ __launch_bounds__(128, 1)
void crf_fwd_kernel(const float* __restrict__ y,
                    const float* __restrict__ mask,
                    const float* __restrict__ trans,
                    float* __restrict__ out,
                    int T) {
    const int b    = blockIdx.x;
    const int i    = threadIdx.x;      // 0..127 : output state
    const int lane = i & 31;
    const int warp = i >> 5;

    __shared__ __align__(16) float pbuf[2][KDIM];
    __shared__ float redf[4];
    __shared__ int   len_sh;

    // ---- one-time: E row = exp(trans[i][:]) as 64 packed f32x2 regs ----
    u64 E2[64];
    {
        const float4* t4 = reinterpret_cast<const float4*>(trans + (size_t)i * KDIM);
        #pragma unroll
        for (int q = 0; q < 32; q++) {
            float4 v = t4[q];
            E2[2*q]   = pack2(expf(v.x), expf(v.y));
            E2[2*q+1] = pack2(expf(v.z), expf(v.w));
        }
    }

    // ---- init state, length ----
    if (i == 0) len_sh = 0;
    float s = (i == 2) ? 1.0f : 0.0f;             // SOS_IDX = 2
    pbuf[0][i] = s;
    __syncthreads();
    {
        const float* mb = mask + (size_t)b * T;
        int cnt = 0;
        for (int t = i; t < T; t += KDIM) cnt += (mb[t] != 0.0f);
        cnt = __reduce_add_sync(0xffffffffu, cnt);
        if (lane == 0) atomicAdd(&len_sh, cnt);
    }
    __syncthreads();
    const int len = len_sh;

    // ---- y prefetch pipeline (3 deep), pointer-increment ----
    const float* yb   = y + (size_t)b * T * KDIM + i;
    const float* yp   = yb + 3 * KDIM;
    const float* yend = yb + (size_t)T * KDIM;
    float ey = 0.0f, y1 = 0.0f, y2 = 0.0f;
    if (len > 0) ey = __expf(yb[0]);
    if (1 < T)   y1 = yb[KDIM];
    if (2 < T)   y2 = yb[2 * KDIM];

    int cur  = 0;
    int eacc = 0;

    for (int t = 0; t < len; t++) {
        // renorm scale from exponent of s_t[3] (broadcast LDS.32; no reduce).
        // Guard covers t=0 (s[3]==0) and denormals: scale 1.0 then.
        unsigned hb = __float_as_uint(pbuf[cur][3]);
        int Ee     = (hb >= 0x00800000u) ? (int)(hb >> 23) : 127;
        float rz   = __uint_as_float((unsigned)(254 - Ee) << 23); // 2^(127-Ee)
        float eyrz = ey * rz;
        eacc      += Ee - 127;

        // matvec: q_i = sum_j E[i][j] * s_t[j]  (32x LDS.128 + 64x fma.f32x2,
        // 8 independent accumulator chains)
        const ulonglong2* p2 = reinterpret_cast<const ulonglong2*>(pbuf[cur]);
        u64 a0=0,a1=0,a2=0,a3=0,a4=0,a5=0,a6=0,a7=0;
        #pragma unroll
        for (int q = 0; q < 8; q++) {
            ulonglong2 v0 = p2[4*q+0];
            ulonglong2 v1 = p2[4*q+1];
            ulonglong2 v2 = p2[4*q+2];
            ulonglong2 v3 = p2[4*q+3];
            fma2(a0, E2[8*q+0], v0.x);
            fma2(a1, E2[8*q+1], v0.y);
            fma2(a2, E2[8*q+2], v1.x);
            fma2(a3, E2[8*q+3], v1.y);
            fma2(a4, E2[8*q+4], v2.x);
            fma2(a5, E2[8*q+5], v2.y);
            fma2(a6, E2[8*q+6], v3.x);
            fma2(a7, E2[8*q+7], v3.y);
        }
        u64 aa = add2(add2(add2(a0,a1), add2(a2,a3)),
                      add2(add2(a4,a5), add2(a6,a7)));
        float qlo, qhi;
        asm("mov.b64 {%0, %1}, %2;" : "=f"(qlo), "=f"(qhi) : "l"(aa));
        s = (qlo + qhi) * eyrz;                     // s >= 0 always
        pbuf[cur ^ 1][i] = s;                       // straight to barrier

        // rotate y pipeline (independent; fills issue while STS drains)
        ey = __expf(y1);
        y1 = y2;
        y2 = (yp < yend) ? *yp : 0.0f;
        yp += KDIM;

        __syncthreads();
        cur ^= 1;
    }

    // ---- final: out[b] = log(sum_i s_i) + eacc*ln2 ----
    float e = s;
    e += __shfl_xor_sync(0xffffffffu, e, 16);
    e += __shfl_xor_sync(0xffffffffu, e, 8);
    e += __shfl_xor_sync(0xffffffffu, e, 4);
    e += __shfl_xor_sync(0xffffffffu, e, 2);
    e += __shfl_xor_sync(0xffffffffu, e, 1);
    if (lane == 0) redf[warp] = e;
    __syncthreads();
    if (i == 0) {
        float tot = (redf[0] + redf[1]) + (redf[2] + redf[3]);
        out[b] = logf(tot) + (float)((double)eacc * 0.6931471805599453);
    }
}

extern "C" void kernel_launch(void* const* d_in, const int* in_sizes, int n_in,
                              void* d_out, int out_size) {
    const float* y     = (const float*)d_in[0];   // (B, T, K) f32
    const float* mask  = (const float*)d_in[1];   // (B, T)    f32
    const float* trans = (const float*)d_in[2];   // (K, K)    f32
    float* out = (float*)d_out;                   // (B,)      f32

    const int B = out_size;                       // 64
    const int T = in_sizes[1] / B;                // 256

    crf_fwd_kernel<<<B, 128>>>(y, mask, trans, out, T);
}

// round 10
// speedup vs baseline: 1.2683x; 1.0765x over previous
#include <cuda_runtime.h>

// CRF forward scan, probability domain (scaled HMM forward).
// Champion frame (R7, 59.87us): 1 CTA/batch, 128 threads, full E-row per
// thread as 64 packed f32x2 regs, 8 accumulator chains, every-step
// power-of-two renorm via REDUX.MAX, one __syncthreads per step.
// R10: time loop unrolled x2 with STATIC buffer roles (pbuf[0]->pbuf[1],
// pbuf[1]->pbuf[0]) -- removes cur^=1, dynamic buffer addressing and half
// the loop induction/branch overhead per step. Odd tail peeled.

#define KDIM 128
typedef unsigned long long u64;

__device__ __forceinline__ void fma2(u64& a, u64 x, u64 p) {
    asm("fma.rn.f32x2 %0, %1, %2, %0;" : "+l"(a) : "l"(x), "l"(p));
}
__device__ __forceinline__ u64 add2(u64 a, u64 b) {
    u64 r; asm("add.rn.f32x2 %0, %1, %2;" : "=l"(r) : "l"(a), "l"(b)); return r;
}
__device__ __forceinline__ u64 pack2(float lo, float hi) {
    u64 r; asm("mov.b64 %0, {%1, %2};" : "=l"(r) : "f"(lo), "f"(hi)); return r;
}

__global__ __launch_bounds__(128, 1)
void crf_fwd_kernel(const float* __restrict__ y,
                    const float* __restrict__ mask,
                    const float* __restrict__ trans,
                    float* __restrict__ out,
                    int T) {
    const int b    = blockIdx.x;
    const int i    = threadIdx.x;      // 0..127 : output state
    const int lane = i & 31;
    const int warp = i >> 5;

    __shared__ __align__(16) float    pbuf[2][KDIM];
    __shared__ __align__(16) unsigned wmax[2][4];
    __shared__ float redf[4];
    __shared__ int   len_sh;

    // ---- one-time: E row = exp(trans[i][:]) as 64 packed f32x2 regs ----
    u64 E2[64];
    {
        const float4* t4 = reinterpret_cast<const float4*>(trans + (size_t)i * KDIM);
        #pragma unroll
        for (int q = 0; q < 32; q++) {
            float4 v = t4[q];
            E2[2*q]   = pack2(expf(v.x), expf(v.y));
            E2[2*q+1] = pack2(expf(v.z), expf(v.w));
        }
    }

    // ---- init state, renorm buffer, length ----
    if (i == 0) len_sh = 0;
    pbuf[0][i] = (i == 2) ? 1.0f : 0.0f;          // SOS_IDX = 2
    if (i < 4) wmax[0][i] = 0x3f800000u;          // Z_0 = 1.0
    __syncthreads();
    {
        const float* mb = mask + (size_t)b * T;
        int cnt = 0;
        for (int t = i; t < T; t += KDIM) cnt += (mb[t] != 0.0f);
        cnt = __reduce_add_sync(0xffffffffu, cnt);
        if (lane == 0) atomicAdd(&len_sh, cnt);
    }
    __syncthreads();
    const int len = len_sh;

    // ---- y prefetch pipeline (3 deep), pointer-increment ----
    const float* yb   = y + (size_t)b * T * KDIM + i;
    const float* yp   = yb + 3 * KDIM;
    const float* yend = yb + (size_t)T * KDIM;
    float ey = 0.0f, y1 = 0.0f, y2 = 0.0f;
    if (len > 0) ey = __expf(yb[0]);
    if (1 < T)   y1 = yb[KDIM];
    if (2 < T)   y2 = yb[2 * KDIM];

    int eacc = 0;
    float s;

    // one full step: reads pbuf[SRC], writes pbuf[DST]; SRC/DST compile-time
#define STEP(SRC, DST)                                                        \
    {                                                                         \
        uint4 wm4 = *reinterpret_cast<const uint4*>(wmax[SRC]);               \
        unsigned mbits = max(max(wm4.x, wm4.y), max(wm4.z, wm4.w));           \
        int Ee     = (int)(mbits >> 23);                                      \
        float rz   = __uint_as_float((unsigned)(254 - Ee) << 23);             \
        float eyrz = ey * rz;                                                 \
        eacc      += Ee - 127;                                                \
        const ulonglong2* p2 = reinterpret_cast<const ulonglong2*>(pbuf[SRC]);\
        u64 a0=0,a1=0,a2=0,a3=0,a4=0,a5=0,a6=0,a7=0;                          \
        _Pragma("unroll")                                                     \
        for (int q = 0; q < 8; q++) {                                         \
            ulonglong2 v0 = p2[4*q+0];                                        \
            ulonglong2 v1 = p2[4*q+1];                                        \
            ulonglong2 v2 = p2[4*q+2];                                        \
            ulonglong2 v3 = p2[4*q+3];                                        \
            fma2(a0, E2[8*q+0], v0.x);                                        \
            fma2(a1, E2[8*q+1], v0.y);                                        \
            fma2(a2, E2[8*q+2], v1.x);                                        \
            fma2(a3, E2[8*q+3], v1.y);                                        \
            fma2(a4, E2[8*q+4], v2.x);                                        \
            fma2(a5, E2[8*q+5], v2.y);                                        \
            fma2(a6, E2[8*q+6], v3.x);                                        \
            fma2(a7, E2[8*q+7], v3.y);                                        \
        }                                                                     \
        u64 aa = add2(add2(add2(a0,a1), add2(a2,a3)),                         \
                      add2(add2(a4,a5), add2(a6,a7)));                        \
        float qlo, qhi;                                                       \
        asm("mov.b64 {%0, %1}, %2;" : "=f"(qlo), "=f"(qhi) : "l"(aa));        \
        s = (qlo + qhi) * eyrz;                                               \
        pbuf[DST][i] = s;                                                     \
        unsigned wmv = __reduce_max_sync(0xffffffffu, __float_as_uint(s));    \
        if (lane == 0) wmax[DST][warp] = wmv;                                 \
        ey = __expf(y1);                                                      \
        y1 = y2;                                                              \
        y2 = (yp < yend) ? *yp : 0.0f;                                        \
        yp += KDIM;                                                           \
        __syncthreads();                                                      \
    }

    const int len2 = len & ~1;
    for (int t = 0; t < len2; t += 2) {
        STEP(0, 1)
        STEP(1, 0)
    }
    int cur = 0;
    if (len & 1) {
        STEP(0, 1)
        cur = 1;
    }
#undef STEP

    // ---- final: out[b] = log(sum_i s_i) + eacc*ln2 ----
    float e = pbuf[cur][i];
    e += __shfl_xor_sync(0xffffffffu, e, 16);
    e += __shfl_xor_sync(0xffffffffu, e, 8);
    e += __shfl_xor_sync(0xffffffffu, e, 4);
    e += __shfl_xor_sync(0xffffffffu, e, 2);
    e += __shfl_xor_sync(0xffffffffu, e, 1);
    if (lane == 0) redf[warp] = e;
    __syncthreads();
    if (i == 0) {
        float tot = (redf[0] + redf[1]) + (redf[2] + redf[3]);
        out[b] = logf(tot) + (float)((double)eacc * 0.6931471805599453);
    }
}

extern "C" void kernel_launch(void* const* d_in, const int* in_sizes, int n_in,
                              void* d_out, int out_size) {
    const float* y     = (const float*)d_in[0];   // (B, T, K) f32
    const float* mask  = (const float*)d_in[1];   // (B, T)    f32
    const float* trans = (const float*)d_in[2];   // (K, K)    f32
    float* out = (float*)d_out;                   // (B,)      f32

    const int B = out_size;                       // 64
    const int T = in_sizes[1] / B;                // 256

    crf_fwd_kernel<<<B, 128>>>(y, mask, trans, out, T);
}

// round 11
// speedup vs baseline: 1.6000x; 1.2615x over previous
#include <cuda_runtime.h>
#include <cuda_bf16.h>

// CRF forward scan, probability domain. Matvec on the TENSOR pipe:
// mma.sync.m16n8k16 (bf16 x bf16 -> f32). Warp w computes states
// [32w, 32w+32). B-fragment broadcast trick: all 8 N-columns hold the same
// state vector s, so every lane's C fragment holds valid q = E·s values
// (lane g owns states 32w + g/4 + {0,8,16,24}, 4x redundant per group).
// State vector in SMEM as bf16 (range == fp32 -> lag-1 power-of-two renorm
// unchanged, no overflow). 1 CTA/batch, 128 threads, unroll x2 static
// buffers, every-step REDUX renorm, one __syncthreads per step.

#define KDIM 128

__device__ __forceinline__ unsigned bpack(float lo, float hi) {
    unsigned r;
    asm("cvt.rn.bf16x2.f32 %0, %1, %2;" : "=r"(r) : "f"(hi), "f"(lo));
    return r;
}

#define MMA(C, A, Bv)                                                        \
    asm volatile(                                                            \
        "mma.sync.aligned.m16n8k16.row.col.f32.bf16.bf16.f32 "               \
        "{%0,%1,%2,%3},{%4,%5,%6,%7},{%8,%9},{%0,%1,%2,%3};"                 \
        : "+f"(C[0]), "+f"(C[1]), "+f"(C[2]), "+f"(C[3])                     \
        : "r"(A[0]), "r"(A[1]), "r"(A[2]), "r"(A[3]),                        \
          "r"(Bv[0]), "r"(Bv[1]))

__global__ __launch_bounds__(128, 1)
void crf_fwd_kernel(const float* __restrict__ y,
                    const float* __restrict__ mask,
                    const float* __restrict__ trans,
                    float* __restrict__ out,
                    int T) {
    const int b    = blockIdx.x;
    const int tid  = threadIdx.x;
    const int lane = tid & 31;
    const int warp = tid >> 5;          // 0..3 : states [32w, 32w+32)
    const int g4   = lane >> 2;         // 0..7
    const int tig  = lane & 3;          // 0..3

    __shared__ __align__(16) __nv_bfloat16 sh[2][KDIM];
    __shared__ __align__(16) unsigned wmax[2][4];
    __shared__ float redf[4];
    __shared__ int   len_sh;

    // ---- one-time: E = exp(trans) as mma A-fragments (bf16), 64 regs ----
    // A frag (m16n8k16): rows r0=base+g4, r1=r0+8; cols c0=16kt+2tig (+1,+8,+9)
    unsigned EA[2][8][4];
    #pragma unroll
    for (int mt = 0; mt < 2; mt++) {
        const int r0 = 32 * warp + 16 * mt + g4;
        const float* tr0 = trans + (size_t)r0 * KDIM;
        const float* tr1 = tr0 + 8 * KDIM;
        #pragma unroll
        for (int kt = 0; kt < 8; kt++) {
            const int c0 = 16 * kt + 2 * tig;
            EA[mt][kt][0] = bpack(expf(tr0[c0]),   expf(tr0[c0+1]));
            EA[mt][kt][1] = bpack(expf(tr1[c0]),   expf(tr1[c0+1]));
            EA[mt][kt][2] = bpack(expf(tr0[c0+8]), expf(tr0[c0+9]));
            EA[mt][kt][3] = bpack(expf(tr1[c0+8]), expf(tr1[c0+9]));
        }
    }

    // ---- init state, renorm buffers, length ----
    if (tid == 0) len_sh = 0;
    if (tid < KDIM) sh[0][tid] = __float2bfloat16_rn((tid == 2) ? 1.0f : 0.0f);
    if (tid < 8) wmax[tid >> 2][tid & 3] = 0x3f800000u;   // both slots = 1.0
    __syncthreads();
    {
        const float* mb = mask + (size_t)b * T;
        int cnt = 0;
        for (int t = tid; t < T; t += KDIM) cnt += (mb[t] != 0.0f);
        cnt = __reduce_add_sync(0xffffffffu, cnt);
        if (lane == 0) atomicAdd(&len_sh, cnt);
    }
    __syncthreads();
    const int len = len_sh;

    // ---- y prefetch pipeline (3 deep); thread owns 4 states: m0+{0,8,16,24}
    const int m0 = 32 * warp + g4;
    const float* yb   = y + (size_t)b * T * KDIM + m0;
    const float* yp   = yb + 3 * KDIM;
    const float* yend = yb + (size_t)T * KDIM;
    float ey[4], yA[4], yB[4];
    #pragma unroll
    for (int k = 0; k < 4; k++) {
        ey[k] = (len > 0) ? __expf(yb[8 * k]) : 1.0f;
        yA[k] = (1 < T) ? yb[KDIM + 8 * k]     : 0.0f;
        yB[k] = (2 < T) ? yb[2 * KDIM + 8 * k] : 0.0f;
    }

    // live state (fp32) for the 4 owned states (4x redundant per group)
    float s0 = (warp == 0 && g4 == 2) ? 1.0f : 0.0f;   // SOS_IDX = 2
    float s1 = 0.0f, s2 = 0.0f, s3 = 0.0f;
    int eacc = 0;

#define STEP(SRC, DST)                                                       \
    {                                                                        \
        uint4 wm4 = *reinterpret_cast<const uint4*>(wmax[SRC]);              \
        unsigned mbits = max(max(wm4.x, wm4.y), max(wm4.z, wm4.w));          \
        int Ee   = (int)(mbits >> 23);                                       \
        float rz = __uint_as_float((unsigned)(254 - Ee) << 23);              \
        eacc    += Ee - 127;                                                 \
        float ez0 = ey[0]*rz, ez1 = ey[1]*rz, ez2 = ey[2]*rz, ez3 = ey[3]*rz;\
        /* B fragments: u32 idx = 8*kt + tig (rows 2tig,+1), +4 (rows +8,+9)*/\
        unsigned rb[8][2];                                                   \
        const unsigned* spb = reinterpret_cast<const unsigned*>(sh[SRC]) + tig;\
        _Pragma("unroll")                                                    \
        for (int kt = 0; kt < 8; kt++) {                                     \
            rb[kt][0] = spb[8 * kt];                                         \
            rb[kt][1] = spb[8 * kt + 4];                                     \
        }                                                                    \
        float cP0[4] = {0,0,0,0}, cQ0[4] = {0,0,0,0};                        \
        float cP1[4] = {0,0,0,0}, cQ1[4] = {0,0,0,0};                        \
        _Pragma("unroll")                                                    \
        for (int kp = 0; kp < 4; kp++) {                                     \
            MMA(cP0, EA[0][2*kp],   rb[2*kp]);                               \
            MMA(cP1, EA[1][2*kp],   rb[2*kp]);                               \
            MMA(cQ0, EA[0][2*kp+1], rb[2*kp+1]);                             \
            MMA(cQ1, EA[1][2*kp+1], rb[2*kp+1]);                             \
        }                                                                    \
        s0 = (cP0[0] + cQ0[0]) * ez0;   /* state m0      */                  \
        s1 = (cP0[2] + cQ0[2]) * ez1;   /* state m0 + 8  */                  \
        s2 = (cP1[0] + cQ1[0]) * ez2;   /* state m0 + 16 */                  \
        s3 = (cP1[2] + cQ1[2]) * ez3;   /* state m0 + 24 */                  \
        __nv_bfloat16* sd = sh[DST] + m0;                                    \
        sd[0]  = __float2bfloat16_rn(s0);                                    \
        sd[8]  = __float2bfloat16_rn(s1);                                    \
        sd[16] = __float2bfloat16_rn(s2);                                    \
        sd[24] = __float2bfloat16_rn(s3);                                    \
        unsigned mm = max(max(__float_as_uint(s0), __float_as_uint(s1)),     \
                          max(__float_as_uint(s2), __float_as_uint(s3)));    \
        mm = __reduce_max_sync(0xffffffffu, mm);                             \
        if (lane == 0) wmax[DST][warp] = mm;                                 \
        _Pragma("unroll")                                                    \
        for (int k = 0; k < 4; k++) {                                        \
            ey[k] = __expf(yA[k]);                                           \
            yA[k] = yB[k];                                                   \
            yB[k] = (yp < yend) ? yp[8 * k] : 0.0f;                          \
        }                                                                    \
        yp += KDIM;                                                          \
        __syncthreads();                                                     \
    }

    const int len2 = len & ~1;
    for (int t = 0; t < len2; t += 2) {
        STEP(0, 1)
        STEP(1, 0)
    }
    if (len & 1) {
        STEP(0, 1)
    }
#undef STEP

    // ---- final: out[b] = log(sum_i s_i) + eacc*ln2 ----
    // each state held by 4 lanes -> warp sum = 4 * true partial sum
    float e = (s0 + s1) + (s2 + s3);
    e += __shfl_xor_sync(0xffffffffu, e, 16);
    e += __shfl_xor_sync(0xffffffffu, e, 8);
    e += __shfl_xor_sync(0xffffffffu, e, 4);
    e += __shfl_xor_sync(0xffffffffu, e, 2);
    e += __shfl_xor_sync(0xffffffffu, e, 1);
    if (lane == 0) redf[warp] = e;
    __syncthreads();
    if (tid == 0) {
        float tot = ((redf[0] + redf[1]) + (redf[2] + redf[3])) * 0.25f;
        out[b] = logf(tot) + (float)((double)eacc * 0.6931471805599453);
    }
}

extern "C" void kernel_launch(void* const* d_in, const int* in_sizes, int n_in,
                              void* d_out, int out_size) {
    const float* y     = (const float*)d_in[0];   // (B, T, K) f32
    const float* mask  = (const float*)d_in[1];   // (B, T)    f32
    const float* trans = (const float*)d_in[2];   // (K, K)    f32
    float* out = (float*)d_out;                   // (B,)      f32

    const int B = out_size;                       // 64
    const int T = in_sizes[1] / B;                // 256

    crf_fwd_kernel<<<B, 128>>>(y, mask, trans, out, T);
}